// round 4
// baseline (speedup 1.0000x reference)
#include <cuda_runtime.h>
#include <cstdint>

// ---------------------------------------------------------------------------
// Problem dims (fixed): B=4, L=4096, H=1024, F=4096
// ---------------------------------------------------------------------------
constexpr int TT = 16384;   // tokens
constexpr int HD = 1024;
constexpr int FD = 4096;

constexpr int BM = 128, BN = 128, BK = 32;
constexpr int STAGES = 3;
constexpr int A_ELEMS = BM * BK;            // 4096 floats, 16 KB
constexpr int B_ELEMS = BN * BK;
constexpr int SMEM_FLOATS = STAGES * (A_ELEMS + B_ELEMS);
constexpr int SMEM_BYTES  = SMEM_FLOATS * 4; // 96 KB

// ---------------------------------------------------------------------------
// Scratch (allocation-free rule: module-scope device globals)
// ---------------------------------------------------------------------------
__device__ __align__(1024) float g_Xr [(size_t)TT * HD];   //  64 MB rounded X
__device__ __align__(1024) float g_W1T[(size_t)FD * HD];   //  16 MB W1^T
__device__ __align__(1024) float g_W2T[(size_t)HD * FD];   //  16 MB W2^T
__device__ __align__(1024) float g_H  [(size_t)TT * FD];   // 268 MB hidden

// ---------------------------------------------------------------------------
// Helpers
// ---------------------------------------------------------------------------
__device__ __forceinline__ uint32_t smem_u32(const void* p) {
    uint32_t a;
    asm("{ .reg .u64 t; cvta.to.shared.u64 t, %1; cvt.u32.u64 %0, t; }" : "=r"(a) : "l"(p));
    return a;
}

__device__ __forceinline__ void cp_async16(uint32_t smem_addr, const void* gptr) {
    asm volatile("cp.async.cg.shared.global [%0], [%1], 16;"
                 :: "r"(smem_addr), "l"(gptr) : "memory");
}
#define CP_COMMIT() asm volatile("cp.async.commit_group;" ::: "memory")
#define CP_WAIT(n)  asm volatile("cp.async.wait_group %0;" :: "n"(n) : "memory")

// Round-to-nearest-even fp32 -> tf32 (exactly representable in tf32)
__device__ __forceinline__ float rne_tf32(float f) {
    uint32_t u = __float_as_uint(f);
    u = (u + 0xFFFu + ((u >> 13) & 1u)) & 0xFFFFE000u;
    return __uint_as_float(u);
}

// XOR swizzle: tile is [rows][32 floats]; permute 16B chunks per row.
__device__ __forceinline__ int sw(int row, int col) {
    return row * BK + (col ^ ((row & 7) << 2));
}

__device__ __forceinline__ void mma_tf32(float* c, uint32_t a0, uint32_t a1,
                                         uint32_t a2, uint32_t a3,
                                         uint32_t b0, uint32_t b1) {
    asm volatile(
        "mma.sync.aligned.m16n8k8.row.col.f32.tf32.tf32.f32 "
        "{%0,%1,%2,%3}, {%4,%5,%6,%7}, {%8,%9}, {%0,%1,%2,%3};"
        : "+f"(c[0]), "+f"(c[1]), "+f"(c[2]), "+f"(c[3])
        : "r"(a0), "r"(a1), "r"(a2), "r"(a3), "r"(b0), "r"(b1));
}

// ---------------------------------------------------------------------------
// Prepass kernels
// ---------------------------------------------------------------------------
__global__ void round_tf32_kernel(const float* __restrict__ in, float* __restrict__ out, int n4) {
    int i = blockIdx.x * blockDim.x + threadIdx.x;
    if (i < n4) {
        float4 v = reinterpret_cast<const float4*>(in)[i];
        v.x = rne_tf32(v.x); v.y = rne_tf32(v.y);
        v.z = rne_tf32(v.z); v.w = rne_tf32(v.w);
        reinterpret_cast<float4*>(out)[i] = v;
    }
}

// dst[c][r] = rne_tf32(src[r][c]);  src is [R][C]
__global__ void transpose_round_kernel(const float* __restrict__ src, float* __restrict__ dst,
                                       int R, int C) {
    __shared__ float tile[32][33];
    int c0 = blockIdx.x * 32, r0 = blockIdx.y * 32;
    int tx = threadIdx.x, ty = threadIdx.y;
#pragma unroll
    for (int i = 0; i < 4; i++)
        tile[ty + i * 8][tx] = rne_tf32(src[(size_t)(r0 + ty + i * 8) * C + c0 + tx]);
    __syncthreads();
#pragma unroll
    for (int i = 0; i < 4; i++)
        dst[(size_t)(c0 + ty + i * 8) * R + r0 + tx] = tile[tx][ty + i * 8];
}

// ---------------------------------------------------------------------------
// tf32 GEMM:  D[m][n] = sum_k A[m][k] * Bt[n][k]
//   mode 0: dst = rne_tf32(relu(acc + bias[n]))   (writes H)
//   mode 1: dst = padding[row] ? 0 : acc + bias[n]
// ---------------------------------------------------------------------------
__global__ void __launch_bounds__(256, 2)
gemm_tf32_kernel(const float* __restrict__ A, const float* __restrict__ Bt,
                 const float* __restrict__ bias, const int* __restrict__ padding,
                 float* __restrict__ dst, int K, int N, int mode) {
    extern __shared__ float smem[];
    const uint32_t smem_base = smem_u32(smem);
    const int tid  = threadIdx.x;
    const int lane = tid & 31;
    const int wid  = tid >> 5;
    const int warp_m = wid & 1;        // 2 warps along M
    const int warp_n = wid >> 1;       // 4 warps along N
    const int m0 = blockIdx.y * BM;
    const int n0 = blockIdx.x * BN;

    // stage offsets (floats)
    auto sA_off = [&](int s) { return s * A_ELEMS; };
    auto sB_off = [&](int s) { return STAGES * A_ELEMS + s * B_ELEMS; };

    const int NUM_CHUNKS = K / BK;

    auto load_stage = [&](int chunk, int s) {
        int k0 = chunk * BK;
#pragma unroll
        for (int t = 0; t < 4; t++) {
            int idx = tid + t * 256;
            int row = idx >> 3, c4 = idx & 7;
            int scol = (c4 * 4) ^ ((row & 7) << 2);
            cp_async16(smem_base + (sA_off(s) + row * BK + scol) * 4,
                       A + (size_t)(m0 + row) * K + k0 + c4 * 4);
        }
#pragma unroll
        for (int t = 0; t < 4; t++) {
            int idx = tid + t * 256;
            int row = idx >> 3, c4 = idx & 7;
            int scol = (c4 * 4) ^ ((row & 7) << 2);
            cp_async16(smem_base + (sB_off(s) + row * BK + scol) * 4,
                       Bt + (size_t)(n0 + row) * K + k0 + c4 * 4);
        }
    };

    // prologue: STAGES-1 chunks in flight
#pragma unroll
    for (int s = 0; s < STAGES - 1; s++) {
        load_stage(s, s);
        CP_COMMIT();
    }

    float acc[4][4][4];
#pragma unroll
    for (int mt = 0; mt < 4; mt++)
#pragma unroll
        for (int nt = 0; nt < 4; nt++)
#pragma unroll
            for (int j = 0; j < 4; j++) acc[mt][nt][j] = 0.f;

    const uint32_t* sAu = reinterpret_cast<const uint32_t*>(smem);
    const uint32_t* sBu = sAu;   // same array, different offsets

    for (int c = 0; c < NUM_CHUNKS; c++) {
        CP_WAIT(STAGES - 2);          // chunk c resident
        __syncthreads();
        int next = c + STAGES - 1;
        if (next < NUM_CHUNKS) load_stage(next, next % STAGES);
        CP_COMMIT();

        const int s = c % STAGES;
        const int aBase = sA_off(s);
        const int bBase = sB_off(s);
        const int ra = warp_m * 64 + (lane >> 2);
        const int nb = warp_n * 32 + (lane >> 2);
        const int kc0 = lane & 3;

#pragma unroll
        for (int ks = 0; ks < 4; ks++) {
            const int kc = ks * 8 + kc0;
            uint32_t a[4][4], b[4][2];
#pragma unroll
            for (int mt = 0; mt < 4; mt++) {
                int r0 = ra + mt * 16;
                a[mt][0] = sAu[aBase + sw(r0,     kc)];
                a[mt][1] = sAu[aBase + sw(r0 + 8, kc)];
                a[mt][2] = sAu[aBase + sw(r0,     kc + 4)];
                a[mt][3] = sAu[aBase + sw(r0 + 8, kc + 4)];
            }
#pragma unroll
            for (int nt = 0; nt < 4; nt++) {
                int n = nb + nt * 8;
                b[nt][0] = sBu[bBase + sw(n, kc)];
                b[nt][1] = sBu[bBase + sw(n, kc + 4)];
            }
#pragma unroll
            for (int mt = 0; mt < 4; mt++)
#pragma unroll
                for (int nt = 0; nt < 4; nt++)
                    mma_tf32(acc[mt][nt], a[mt][0], a[mt][1], a[mt][2], a[mt][3],
                             b[nt][0], b[nt][1]);
        }
        __syncthreads();
    }

    // ---- epilogue ----
#pragma unroll
    for (int mt = 0; mt < 4; mt++) {
        int row0 = m0 + warp_m * 64 + mt * 16 + (lane >> 2);
#pragma unroll
        for (int half = 0; half < 2; half++) {
            int row = row0 + half * 8;
            int pad = (mode == 1) ? padding[row] : 0;
            float* drow = dst + (size_t)row * N;
#pragma unroll
            for (int nt = 0; nt < 4; nt++) {
                int col = n0 + warp_n * 32 + nt * 8 + (lane & 3) * 2;
                float2 bv = *reinterpret_cast<const float2*>(bias + col);
                float v0 = acc[mt][nt][half * 2 + 0] + bv.x;
                float v1 = acc[mt][nt][half * 2 + 1] + bv.y;
                if (mode == 0) {
                    v0 = rne_tf32(fmaxf(v0, 0.f));
                    v1 = rne_tf32(fmaxf(v1, 0.f));
                } else if (pad != 0) {
                    v0 = 0.f; v1 = 0.f;
                }
                *reinterpret_cast<float2*>(drow + col) = make_float2(v0, v1);
            }
        }
    }
}

// ---------------------------------------------------------------------------
// Host side
// ---------------------------------------------------------------------------
extern "C" void kernel_launch(void* const* d_in, const int* in_sizes, int n_in,
                              void* d_out, int out_size) {
    const float* x   = (const float*)d_in[0];
    const int*   pad = (const int*)  d_in[1];
    const float* W1  = (const float*)d_in[2];
    const float* b1  = (const float*)d_in[3];
    const float* W2  = (const float*)d_in[4];
    const float* b2  = (const float*)d_in[5];
    float*       out = (float*)d_out;

    void *pXr, *pW1T, *pW2T, *pH;
    cudaGetSymbolAddress(&pXr,  g_Xr);
    cudaGetSymbolAddress(&pW1T, g_W1T);
    cudaGetSymbolAddress(&pW2T, g_W2T);
    cudaGetSymbolAddress(&pH,   g_H);

    cudaFuncSetAttribute(gemm_tf32_kernel,
                         cudaFuncAttributeMaxDynamicSharedMemorySize, SMEM_BYTES);

    // Prepass: round X; transpose+round W1, W2
    round_tf32_kernel<<<(TT * HD / 4 + 255) / 256, 256>>>(x, (float*)pXr, TT * HD / 4);
    transpose_round_kernel<<<dim3(FD / 32, HD / 32), dim3(32, 8)>>>(W1, (float*)pW1T, HD, FD);
    transpose_round_kernel<<<dim3(HD / 32, FD / 32), dim3(32, 8)>>>(W2, (float*)pW2T, FD, HD);

    // GEMM1: H = rne_tf32(relu(X @ W1 + b1))
    gemm_tf32_kernel<<<dim3(FD / BN, TT / BM), 256, SMEM_BYTES>>>(
        (const float*)pXr, (const float*)pW1T, b1, nullptr, (float*)pH, HD, FD, 0);

    // GEMM2: out = mask(H @ W2 + b2)
    gemm_tf32_kernel<<<dim3(HD / BN, TT / BM), 256, SMEM_BYTES>>>(
        (const float*)pH, (const float*)pW2T, b2, pad, out, FD, HD, 1);
}

// round 6
// speedup vs baseline: 1.0513x; 1.0513x over previous
#include <cuda_runtime.h>
#include <cstdint>

// ---------------------------------------------------------------------------
// Problem dims (fixed): B=4, L=4096, H=1024, F=4096
// ---------------------------------------------------------------------------
constexpr int TT = 16384;   // tokens
constexpr int HD = 1024;
constexpr int FD = 4096;

constexpr int BM = 128, BN = 128, BK = 32;
constexpr int STAGES = 3;
constexpr int TILE_FLOATS = BM * BK;          // 4096 floats per 128x32 tile
constexpr int TILE_BYTES  = TILE_FLOATS * 4;  // 16 KB
constexpr int SMEM_BYTES  = STAGES * 2 * TILE_BYTES;  // 96 KB (>= 67584 epi use)

// ---------------------------------------------------------------------------
// Scratch (allocation-free rule: module-scope device globals)
// All stored in fragment-permuted tiled layout (see off_A / off_B).
// ---------------------------------------------------------------------------
__device__ __align__(1024) float g_Xr [(size_t)TT * HD];   //  64 MB
__device__ __align__(1024) float g_W1T[(size_t)FD * HD];   //  16 MB
__device__ __align__(1024) float g_W2T[(size_t)HD * FD];   //  16 MB
__device__ __align__(1024) float g_H  [(size_t)TT * FD];   // 268 MB

// ---------------------------------------------------------------------------
// Helpers
// ---------------------------------------------------------------------------
__device__ __forceinline__ uint32_t smem_u32(const void* p) {
    uint32_t a;
    asm("{ .reg .u64 t; cvta.to.shared.u64 t, %1; cvt.u32.u64 %0, t; }" : "=r"(a) : "l"(p));
    return a;
}

__device__ __forceinline__ void cp_async16(uint32_t smem_addr, const void* gptr) {
    asm volatile("cp.async.cg.shared.global [%0], [%1], 16;"
                 :: "r"(smem_addr), "l"(gptr) : "memory");
}
#define CP_COMMIT() asm volatile("cp.async.commit_group;" ::: "memory")
#define CP_WAIT(n)  asm volatile("cp.async.wait_group %0;" :: "n"(n) : "memory")

__device__ __forceinline__ void lds128(uint32_t* r, uint32_t addr) {
    asm volatile("ld.shared.v4.b32 {%0,%1,%2,%3}, [%4];"
                 : "=r"(r[0]), "=r"(r[1]), "=r"(r[2]), "=r"(r[3]) : "r"(addr));
}
__device__ __forceinline__ void lds64(uint32_t* r, uint32_t addr) {
    asm volatile("ld.shared.v2.b32 {%0,%1}, [%2];"
                 : "=r"(r[0]), "=r"(r[1]) : "r"(addr));
}

// Round-to-nearest-even fp32 -> tf32
__device__ __forceinline__ float rne_tf32(float f) {
    uint32_t u = __float_as_uint(f);
    u = (u + 0xFFFu + ((u >> 13) & 1u)) & 0xFFFFE000u;
    return __uint_as_float(u);
}

__device__ __forceinline__ void mma_tf32(float* c, const uint32_t* a, const uint32_t* b) {
    asm volatile(
        "mma.sync.aligned.m16n8k8.row.col.f32.tf32.tf32.f32 "
        "{%0,%1,%2,%3}, {%4,%5,%6,%7}, {%8,%9}, {%0,%1,%2,%3};"
        : "+f"(c[0]), "+f"(c[1]), "+f"(c[2]), "+f"(c[3])
        : "r"(a[0]), "r"(a[1]), "r"(a[2]), "r"(a[3]), "r"(b[0]), "r"(b[1]));
}

// ---------------------------------------------------------------------------
// Fragment-order layouts within one [128 rows][32 k] tile (4096 floats):
//   A: [ks:4][g:8][lane:32][4]  — a thread's 4 A-regs = one 16B chunk
//   B: [ks:4][ng:16][lane:32][2] — a thread's 2 B-regs = one 8B chunk
// ---------------------------------------------------------------------------
__device__ __forceinline__ int off_A(int r, int kk) {
    int ks = kk >> 3, c = kk & 3, hk = (kk >> 2) & 1;
    int g = r >> 4, rr = r & 15, lh = rr & 7, hm = rr >> 3;
    return (((ks * 8 + g) * 32) + lh * 4 + c) * 4 + hk * 2 + hm;
}
__device__ __forceinline__ int off_B(int n, int kk) {
    int ks = kk >> 3, c = kk & 3, hk = (kk >> 2) & 1;
    int ng = n >> 3, lh = n & 7;
    return (((ks * 16 + ng) * 32) + lh * 4 + c) * 2 + hk;
}

// ---------------------------------------------------------------------------
// Prepass: round + permute into tiled fragment layouts
// ---------------------------------------------------------------------------
// src [M][Ksrc] row-major -> A-perm tiles; tile (mt=by, kt=bx); gridDim.x = Ksrc/32
__global__ void permuteA_kernel(const float* __restrict__ src, float* __restrict__ dst, int Ksrc) {
    __shared__ float sp[TILE_FLOATS];
    int tid = threadIdx.x;
    const float* s0 = src + (size_t)blockIdx.y * 128 * Ksrc + blockIdx.x * 32;
#pragma unroll
    for (int i = 0; i < 16; i++) {
        int idx = tid + i * 256;
        int r = idx >> 5, kk = idx & 31;
        sp[off_A(r, kk)] = rne_tf32(s0[(size_t)r * Ksrc + kk]);
    }
    __syncthreads();
    float4* d4 = (float4*)(dst + ((size_t)blockIdx.y * gridDim.x + blockIdx.x) * TILE_FLOATS);
#pragma unroll
    for (int i = 0; i < 4; i++) d4[tid + i * 256] = ((float4*)sp)[tid + i * 256];
}

// src [Ktot][Nsrc] row-major -> B-perm tiles over [N][K]; tile (ntile=by, kt=bx); gridDim.x = Ktot/32
__global__ void permuteB_kernel(const float* __restrict__ src, float* __restrict__ dst, int Nsrc) {
    __shared__ float sp[TILE_FLOATS];
    int tid = threadIdx.x;
    const float* s0 = src + (size_t)blockIdx.x * 32 * Nsrc + blockIdx.y * 128;
#pragma unroll
    for (int i = 0; i < 16; i++) {
        int idx = tid + i * 256;
        int kk = idx >> 7, nn = idx & 127;
        sp[off_B(nn, kk)] = rne_tf32(s0[(size_t)kk * Nsrc + nn]);
    }
    __syncthreads();
    float4* d4 = (float4*)(dst + ((size_t)blockIdx.y * gridDim.x + blockIdx.x) * TILE_FLOATS);
#pragma unroll
    for (int i = 0; i < 4; i++) d4[tid + i * 256] = ((float4*)sp)[tid + i * 256];
}

// ---------------------------------------------------------------------------
// tf32 GEMM on fragment-permuted tiles:
//   mode 0: dst (A-perm tiles) = rne_tf32(relu(acc + bias))  [writes H for GEMM2]
//   mode 1: dst (natural row-major, width Nnat) = pad ? 0 : acc + bias
// ---------------------------------------------------------------------------
__global__ void __launch_bounds__(256, 2)
gemm_tf32_kernel(const float* __restrict__ A, const float* __restrict__ Bt,
                 const float* __restrict__ bias, const int* __restrict__ padding,
                 float* __restrict__ dst, int numChunks, int Nnat, int ldTiles, int mode) {
    extern __shared__ float smem[];
    const uint32_t smem_base = smem_u32(smem);
    const int tid = threadIdx.x, lane = tid & 31, wid = tid >> 5;
    const int warp_m = wid & 1;        // 2 warps along M
    const int warp_n = wid >> 1;       // 4 warps along N

    const float* aTiles = A  + (size_t)blockIdx.y * numChunks * TILE_FLOATS;
    const float* bTiles = Bt + (size_t)blockIdx.x * numChunks * TILE_FLOATS;

    auto load_stage = [&](int chunk, int s) {
        const float* aT = aTiles + (size_t)chunk * TILE_FLOATS;
        const float* bT = bTiles + (size_t)chunk * TILE_FLOATS;
        uint32_t da = smem_base + s * TILE_BYTES;
        uint32_t db = smem_base + (STAGES + s) * TILE_BYTES;
#pragma unroll
        for (int t = 0; t < 4; t++) {
            int idx = tid + t * 256;
            cp_async16(da + idx * 16, aT + idx * 4);
        }
#pragma unroll
        for (int t = 0; t < 4; t++) {
            int idx = tid + t * 256;
            cp_async16(db + idx * 16, bT + idx * 4);
        }
    };

#pragma unroll
    for (int s = 0; s < STAGES - 1; s++) {
        load_stage(s, s);
        CP_COMMIT();
    }

    float acc[4][4][4];
#pragma unroll
    for (int mt = 0; mt < 4; mt++)
#pragma unroll
        for (int nt = 0; nt < 4; nt++)
#pragma unroll
            for (int j = 0; j < 4; j++) acc[mt][nt][j] = 0.f;

    const uint32_t laneA = lane * 16;
    const uint32_t laneB = lane * 8;

    for (int c = 0; c < numChunks; c++) {
        CP_WAIT(STAGES - 2);
        __syncthreads();
        int next = c + STAGES - 1;
        if (next < numChunks) load_stage(next, next % STAGES);
        CP_COMMIT();

        const int s = c % STAGES;
        const uint32_t aBase = smem_base + s * TILE_BYTES + laneA;
        const uint32_t bBase = smem_base + (STAGES + s) * TILE_BYTES + laneB;

#pragma unroll
        for (int ks = 0; ks < 4; ks++) {
            uint32_t a[4][4], b[4][2];
#pragma unroll
            for (int mt = 0; mt < 4; mt++)
                lds128(a[mt], aBase + (uint32_t)((ks * 8 + warp_m * 4 + mt) * 32) * 16u);
#pragma unroll
            for (int nt = 0; nt < 4; nt++)
                lds64(b[nt], bBase + (uint32_t)((ks * 16 + warp_n * 4 + nt) * 32) * 8u);
#pragma unroll
            for (int mt = 0; mt < 4; mt++)
#pragma unroll
                for (int nt = 0; nt < 4; nt++)
                    mma_tf32(acc[mt][nt], a[mt], b[nt]);
        }
        __syncthreads();
    }

    if (mode == 0) {
        // Stage output tile to smem (natural, padded stride), then write A-perm
        // tiles float4-coalesced so GEMM2 can consume H directly.
        const int LDSN = 132;               // pad -> conflict-free readback
        float* snat = smem;                 // 128*132*4 = 67584 B <= 96 KB
#pragma unroll
        for (int mt = 0; mt < 4; mt++) {
            int r0 = warp_m * 64 + mt * 16 + (lane >> 2);
#pragma unroll
            for (int hm = 0; hm < 2; hm++) {
                int r = r0 + hm * 8;
#pragma unroll
                for (int nt = 0; nt < 4; nt++) {
                    int col = warp_n * 32 + nt * 8 + (lane & 3) * 2;
                    float2 bv = *reinterpret_cast<const float2*>(bias + blockIdx.x * BN + col);
                    snat[r * LDSN + col]     = rne_tf32(fmaxf(acc[mt][nt][hm * 2 + 0] + bv.x, 0.f));
                    snat[r * LDSN + col + 1] = rne_tf32(fmaxf(acc[mt][nt][hm * 2 + 1] + bv.y, 0.f));
                }
            }
        }
        __syncthreads();
#pragma unroll
        for (int kt = 0; kt < 4; kt++) {
            float* dT = dst + ((size_t)blockIdx.y * ldTiles + blockIdx.x * 4 + kt) * TILE_FLOATS;
#pragma unroll
            for (int i = 0; i < 4; i++) {
                int bi = tid + i * 256;              // float4 index in tile
                int lf = bi & 31, rest = bi >> 5;
                int g = rest & 7, ks = rest >> 3;
                int cc = lf & 3, lh = lf >> 2;
                int r = g * 16 + lh, kk = ks * 8 + cc;
                float4 o;
                o.x = snat[r * LDSN + kt * 32 + kk];
                o.y = snat[(r + 8) * LDSN + kt * 32 + kk];
                o.z = snat[r * LDSN + kt * 32 + kk + 4];
                o.w = snat[(r + 8) * LDSN + kt * 32 + kk + 4];
                *reinterpret_cast<float4*>(dT + bi * 4) = o;
            }
        }
    } else {
        // natural row-major output with padding mask
        const int m0 = blockIdx.y * BM, n0 = blockIdx.x * BN;
#pragma unroll
        for (int mt = 0; mt < 4; mt++) {
            int row0 = m0 + warp_m * 64 + mt * 16 + (lane >> 2);
#pragma unroll
            for (int hm = 0; hm < 2; hm++) {
                int row = row0 + hm * 8;
                int pad = padding[row];
                float* drow = dst + (size_t)row * Nnat;
#pragma unroll
                for (int nt = 0; nt < 4; nt++) {
                    int col = n0 + warp_n * 32 + nt * 8 + (lane & 3) * 2;
                    float2 bv = *reinterpret_cast<const float2*>(bias + col);
                    float v0 = acc[mt][nt][hm * 2 + 0] + bv.x;
                    float v1 = acc[mt][nt][hm * 2 + 1] + bv.y;
                    if (pad != 0) { v0 = 0.f; v1 = 0.f; }
                    *reinterpret_cast<float2*>(drow + col) = make_float2(v0, v1);
                }
            }
        }
    }
}

// ---------------------------------------------------------------------------
// Host side
// ---------------------------------------------------------------------------
extern "C" void kernel_launch(void* const* d_in, const int* in_sizes, int n_in,
                              void* d_out, int out_size) {
    const float* x   = (const float*)d_in[0];
    const int*   pad = (const int*)  d_in[1];
    const float* W1  = (const float*)d_in[2];
    const float* b1  = (const float*)d_in[3];
    const float* W2  = (const float*)d_in[4];
    const float* b2  = (const float*)d_in[5];
    float*       out = (float*)d_out;

    void *pXr, *pW1T, *pW2T, *pH;
    cudaGetSymbolAddress(&pXr,  g_Xr);
    cudaGetSymbolAddress(&pW1T, g_W1T);
    cudaGetSymbolAddress(&pW2T, g_W2T);
    cudaGetSymbolAddress(&pH,   g_H);

    cudaFuncSetAttribute(gemm_tf32_kernel,
                         cudaFuncAttributeMaxDynamicSharedMemorySize, SMEM_BYTES);

    // Prepass: round + permute
    permuteA_kernel<<<dim3(HD / 32, TT / 128), 256>>>(x,  (float*)pXr,  HD);
    permuteB_kernel<<<dim3(HD / 32, FD / 128), 256>>>(W1, (float*)pW1T, FD);
    permuteB_kernel<<<dim3(FD / 32, HD / 128), 256>>>(W2, (float*)pW2T, HD);

    // GEMM1: H(A-perm) = rne_tf32(relu(X @ W1 + b1))
    gemm_tf32_kernel<<<dim3(FD / BN, TT / BM), 256, SMEM_BYTES>>>(
        (const float*)pXr, (const float*)pW1T, b1, nullptr, (float*)pH,
        HD / 32, FD, FD / 32, 0);

    // GEMM2: out = mask(H @ W2 + b2)
    gemm_tf32_kernel<<<dim3(HD / BN, TT / BM), 256, SMEM_BYTES>>>(
        (const float*)pH, (const float*)pW2T, b2, pad, out,
        FD / 32, HD, 0, 1);
}

// round 9
// speedup vs baseline: 1.1030x; 1.0492x over previous
#include <cuda_runtime.h>
#include <cstdint>

// ---------------------------------------------------------------------------
// Problem dims (fixed): B=4, L=4096, H=1024, F=4096
// ---------------------------------------------------------------------------
constexpr int TT = 16384;   // tokens
constexpr int HD = 1024;
constexpr int FD = 4096;

constexpr int BM = 128, BN = 128, BK = 32;
constexpr int STAGES = 3;
constexpr int TILE_FLOATS = BM * BK;          // 4096 floats per 128x32 tile
constexpr int TILE_BYTES  = TILE_FLOATS * 4;  // 16 KB
constexpr int SMEM_BYTES  = STAGES * 2 * TILE_BYTES;  // 96 KB (>= 67584 epi use)

// ---------------------------------------------------------------------------
// Scratch (allocation-free rule: module-scope device globals)
// All stored in fragment-permuted tiled layout (see off_A / off_B).
// ---------------------------------------------------------------------------
__device__ __align__(1024) float g_Xr [(size_t)TT * HD];   //  64 MB
__device__ __align__(1024) float g_W1T[(size_t)FD * HD];   //  16 MB
__device__ __align__(1024) float g_W2T[(size_t)HD * FD];   //  16 MB
__device__ __align__(1024) float g_H  [(size_t)TT * FD];   // 268 MB

// ---------------------------------------------------------------------------
// Helpers
// ---------------------------------------------------------------------------
__device__ __forceinline__ uint32_t smem_u32(const void* p) {
    uint32_t a;
    asm("{ .reg .u64 t; cvta.to.shared.u64 t, %1; cvt.u32.u64 %0, t; }" : "=r"(a) : "l"(p));
    return a;
}

__device__ __forceinline__ void cp_async16(uint32_t smem_addr, const void* gptr) {
    asm volatile("cp.async.cg.shared.global [%0], [%1], 16;"
                 :: "r"(smem_addr), "l"(gptr) : "memory");
}
#define CP_COMMIT() asm volatile("cp.async.commit_group;" ::: "memory")
#define CP_WAIT(n)  asm volatile("cp.async.wait_group %0;" :: "n"(n) : "memory")

__device__ __forceinline__ void lds128(uint32_t* r, uint32_t addr) {
    asm volatile("ld.shared.v4.b32 {%0,%1,%2,%3}, [%4];"
                 : "=r"(r[0]), "=r"(r[1]), "=r"(r[2]), "=r"(r[3]) : "r"(addr));
}
__device__ __forceinline__ void lds64(uint32_t* r, uint32_t addr) {
    asm volatile("ld.shared.v2.b32 {%0,%1}, [%2];"
                 : "=r"(r[0]), "=r"(r[1]) : "r"(addr));
}

// Round-to-nearest-even fp32 -> tf32
__device__ __forceinline__ float rne_tf32(float f) {
    uint32_t u = __float_as_uint(f);
    u = (u + 0xFFFu + ((u >> 13) & 1u)) & 0xFFFFE000u;
    return __uint_as_float(u);
}

__device__ __forceinline__ void mma_tf32(float* c, const uint32_t* a, const uint32_t* b) {
    asm volatile(
        "mma.sync.aligned.m16n8k8.row.col.f32.tf32.tf32.f32 "
        "{%0,%1,%2,%3}, {%4,%5,%6,%7}, {%8,%9}, {%0,%1,%2,%3};"
        : "+f"(c[0]), "+f"(c[1]), "+f"(c[2]), "+f"(c[3])
        : "r"(a[0]), "r"(a[1]), "r"(a[2]), "r"(a[3]), "r"(b[0]), "r"(b[1]));
}

// ---------------------------------------------------------------------------
// Fragment-order layouts within one [128 rows][32 k] tile (4096 floats):
//   A: [ks:4][g:8][lane:32][4]  — a thread's 4 A-regs = one 16B chunk
//   B: [ks:4][ng:16][lane:32][2] — a thread's 2 B-regs = one 8B chunk
// ---------------------------------------------------------------------------
__device__ __forceinline__ int off_A(int r, int kk) {
    int ks = kk >> 3, c = kk & 3, hk = (kk >> 2) & 1;
    int g = r >> 4, rr = r & 15, lh = rr & 7, hm = rr >> 3;
    return (((ks * 8 + g) * 32) + lh * 4 + c) * 4 + hk * 2 + hm;
}
__device__ __forceinline__ int off_B(int n, int kk) {
    int ks = kk >> 3, c = kk & 3, hk = (kk >> 2) & 1;
    int ng = n >> 3, lh = n & 7;
    return (((ks * 16 + ng) * 32) + lh * 4 + c) * 2 + hk;
}

// ---------------------------------------------------------------------------
// Prepass: round + permute into tiled fragment layouts
// ---------------------------------------------------------------------------
// src [M][Ksrc] row-major -> A-perm tiles; tile (mt=by, kt=bx); gridDim.x = Ksrc/32
__global__ void permuteA_kernel(const float* __restrict__ src, float* __restrict__ dst, int Ksrc) {
    __shared__ float sp[TILE_FLOATS];
    int tid = threadIdx.x;
    const float* s0 = src + (size_t)blockIdx.y * 128 * Ksrc + blockIdx.x * 32;
#pragma unroll
    for (int i = 0; i < 16; i++) {
        int idx = tid + i * 256;
        int r = idx >> 5, kk = idx & 31;
        sp[off_A(r, kk)] = rne_tf32(s0[(size_t)r * Ksrc + kk]);
    }
    __syncthreads();
    float4* d4 = (float4*)(dst + ((size_t)blockIdx.y * gridDim.x + blockIdx.x) * TILE_FLOATS);
#pragma unroll
    for (int i = 0; i < 4; i++) d4[tid + i * 256] = ((float4*)sp)[tid + i * 256];
}

// src [Ktot][Nsrc] row-major -> B-perm tiles over [N][K]; tile (ntile=by, kt=bx); gridDim.x = Ktot/32
__global__ void permuteB_kernel(const float* __restrict__ src, float* __restrict__ dst, int Nsrc) {
    __shared__ float sp[TILE_FLOATS];
    int tid = threadIdx.x;
    const float* s0 = src + (size_t)blockIdx.x * 32 * Nsrc + blockIdx.y * 128;
#pragma unroll
    for (int i = 0; i < 16; i++) {
        int idx = tid + i * 256;
        int kk = idx >> 7, nn = idx & 127;
        sp[off_B(nn, kk)] = rne_tf32(s0[(size_t)kk * Nsrc + nn]);
    }
    __syncthreads();
    float4* d4 = (float4*)(dst + ((size_t)blockIdx.y * gridDim.x + blockIdx.x) * TILE_FLOATS);
#pragma unroll
    for (int i = 0; i < 4; i++) d4[tid + i * 256] = ((float4*)sp)[tid + i * 256];
}

// ---------------------------------------------------------------------------
// tf32 GEMM on fragment-permuted tiles:
//   mode 0: dst (A-perm tiles) = rne_tf32(relu(acc + bias))  [writes H for GEMM2]
//   mode 1: dst (natural row-major, width Nnat) = pad ? 0 : acc + bias
// ---------------------------------------------------------------------------
__global__ void __launch_bounds__(256, 2)
gemm_tf32_kernel(const float* __restrict__ A, const float* __restrict__ Bt,
                 const float* __restrict__ bias, const int* __restrict__ padding,
                 float* __restrict__ dst, int numChunks, int Nnat, int ldTiles, int mode) {
    extern __shared__ float smem[];
    const uint32_t smem_base = smem_u32(smem);
    const int tid = threadIdx.x, lane = tid & 31, wid = tid >> 5;
    const int warp_m = wid & 1;        // 2 warps along M
    const int warp_n = wid >> 1;       // 4 warps along N

    const float* aTiles = A  + (size_t)blockIdx.y * numChunks * TILE_FLOATS;
    const float* bTiles = Bt + (size_t)blockIdx.x * numChunks * TILE_FLOATS;

    auto load_stage = [&](int chunk, int s) {
        const float* aT = aTiles + (size_t)chunk * TILE_FLOATS;
        const float* bT = bTiles + (size_t)chunk * TILE_FLOATS;
        uint32_t da = smem_base + s * TILE_BYTES;
        uint32_t db = smem_base + (STAGES + s) * TILE_BYTES;
#pragma unroll
        for (int t = 0; t < 4; t++) {
            int idx = tid + t * 256;
            cp_async16(da + idx * 16, aT + idx * 4);
        }
#pragma unroll
        for (int t = 0; t < 4; t++) {
            int idx = tid + t * 256;
            cp_async16(db + idx * 16, bT + idx * 4);
        }
    };

#pragma unroll
    for (int s = 0; s < STAGES - 1; s++) {
        load_stage(s, s);
        CP_COMMIT();
    }

    float acc[4][4][4];
#pragma unroll
    for (int mt = 0; mt < 4; mt++)
#pragma unroll
        for (int nt = 0; nt < 4; nt++)
#pragma unroll
            for (int j = 0; j < 4; j++) acc[mt][nt][j] = 0.f;

    const uint32_t laneA = lane * 16;
    const uint32_t laneB = lane * 8;

    // double-buffered fragments
    uint32_t afr[2][4][4], bfr[2][4][2];

    auto load_frags = [&](int ks, int buf, uint32_t aBase, uint32_t bBase) {
#pragma unroll
        for (int mt = 0; mt < 4; mt++)
            lds128(afr[buf][mt], aBase + (uint32_t)((ks * 8 + warp_m * 4 + mt) * 32) * 16u);
#pragma unroll
        for (int nt = 0; nt < 4; nt++)
            lds64(bfr[buf][nt], bBase + (uint32_t)((ks * 16 + warp_n * 4 + nt) * 32) * 8u);
    };

    for (int c = 0; c < numChunks; c++) {
        CP_WAIT(STAGES - 2);
        __syncthreads();                 // single barrier per chunk
        int next = c + STAGES - 1;
        if (next < numChunks) load_stage(next, next % STAGES);
        CP_COMMIT();

        const int s = c % STAGES;
        const uint32_t aBase = smem_base + s * TILE_BYTES + laneA;
        const uint32_t bBase = smem_base + (STAGES + s) * TILE_BYTES + laneB;

        load_frags(0, 0, aBase, bBase);
#pragma unroll
        for (int ks = 0; ks < 4; ks++) {
            const int cur = ks & 1;
            if (ks < 3) load_frags(ks + 1, cur ^ 1, aBase, bBase);
#pragma unroll
            for (int mt = 0; mt < 4; mt++)
#pragma unroll
                for (int nt = 0; nt < 4; nt++)
                    mma_tf32(acc[mt][nt], afr[cur][mt], bfr[cur][nt]);
        }
        // no trailing barrier: next iteration's top barrier orders the
        // stage overwrite against this iteration's reads (CUTLASS invariant)
    }
    __syncthreads();                     // protect epilogue smem staging

    if (mode == 0) {
        // Stage output tile to smem (natural, padded stride), then write A-perm
        // tiles float4-coalesced so GEMM2 can consume H directly.
        const int LDSN = 132;               // pad -> conflict-free readback
        float* snat = smem;                 // 128*132*4 = 67584 B <= 96 KB
#pragma unroll
        for (int mt = 0; mt < 4; mt++) {
            int r0 = warp_m * 64 + mt * 16 + (lane >> 2);
#pragma unroll
            for (int hm = 0; hm < 2; hm++) {
                int r = r0 + hm * 8;
#pragma unroll
                for (int nt = 0; nt < 4; nt++) {
                    int col = warp_n * 32 + nt * 8 + (lane & 3) * 2;
                    float2 bv = *reinterpret_cast<const float2*>(bias + blockIdx.x * BN + col);
                    snat[r * LDSN + col]     = rne_tf32(fmaxf(acc[mt][nt][hm * 2 + 0] + bv.x, 0.f));
                    snat[r * LDSN + col + 1] = rne_tf32(fmaxf(acc[mt][nt][hm * 2 + 1] + bv.y, 0.f));
                }
            }
        }
        __syncthreads();
#pragma unroll
        for (int kt = 0; kt < 4; kt++) {
            float* dT = dst + ((size_t)blockIdx.y * ldTiles + blockIdx.x * 4 + kt) * TILE_FLOATS;
#pragma unroll
            for (int i = 0; i < 4; i++) {
                int bi = tid + i * 256;              // float4 index in tile
                int lf = bi & 31, rest = bi >> 5;
                int g = rest & 7, ks = rest >> 3;
                int cc = lf & 3, lh = lf >> 2;
                int r = g * 16 + lh, kk = ks * 8 + cc;
                float4 o;
                o.x = snat[r * LDSN + kt * 32 + kk];
                o.y = snat[(r + 8) * LDSN + kt * 32 + kk];
                o.z = snat[r * LDSN + kt * 32 + kk + 4];
                o.w = snat[(r + 8) * LDSN + kt * 32 + kk + 4];
                *reinterpret_cast<float4*>(dT + bi * 4) = o;
            }
        }
    } else {
        // natural row-major output with padding mask
        const int m0 = blockIdx.y * BM, n0 = blockIdx.x * BN;
#pragma unroll
        for (int mt = 0; mt < 4; mt++) {
            int row0 = m0 + warp_m * 64 + mt * 16 + (lane >> 2);
#pragma unroll
            for (int hm = 0; hm < 2; hm++) {
                int row = row0 + hm * 8;
                int pad = padding[row];
                float* drow = dst + (size_t)row * Nnat;
#pragma unroll
                for (int nt = 0; nt < 4; nt++) {
                    int col = n0 + warp_n * 32 + nt * 8 + (lane & 3) * 2;
                    float2 bv = *reinterpret_cast<const float2*>(bias + col);
                    float v0 = acc[mt][nt][hm * 2 + 0] + bv.x;
                    float v1 = acc[mt][nt][hm * 2 + 1] + bv.y;
                    if (pad != 0) { v0 = 0.f; v1 = 0.f; }
                    *reinterpret_cast<float2*>(drow + col) = make_float2(v0, v1);
                }
            }
        }
    }
}

// ---------------------------------------------------------------------------
// Host side
// ---------------------------------------------------------------------------
extern "C" void kernel_launch(void* const* d_in, const int* in_sizes, int n_in,
                              void* d_out, int out_size) {
    const float* x   = (const float*)d_in[0];
    const int*   pad = (const int*)  d_in[1];
    const float* W1  = (const float*)d_in[2];
    const float* b1  = (const float*)d_in[3];
    const float* W2  = (const float*)d_in[4];
    const float* b2  = (const float*)d_in[5];
    float*       out = (float*)d_out;

    void *pXr, *pW1T, *pW2T, *pH;
    cudaGetSymbolAddress(&pXr,  g_Xr);
    cudaGetSymbolAddress(&pW1T, g_W1T);
    cudaGetSymbolAddress(&pW2T, g_W2T);
    cudaGetSymbolAddress(&pH,   g_H);

    cudaFuncSetAttribute(gemm_tf32_kernel,
                         cudaFuncAttributeMaxDynamicSharedMemorySize, SMEM_BYTES);

    // Prepass: round + permute
    permuteA_kernel<<<dim3(HD / 32, TT / 128), 256>>>(x,  (float*)pXr,  HD);
    permuteB_kernel<<<dim3(HD / 32, FD / 128), 256>>>(W1, (float*)pW1T, FD);
    permuteB_kernel<<<dim3(FD / 32, HD / 128), 256>>>(W2, (float*)pW2T, HD);

    // GEMM1: H(A-perm) = rne_tf32(relu(X @ W1 + b1))
    gemm_tf32_kernel<<<dim3(FD / BN, TT / BM), 256, SMEM_BYTES>>>(
        (const float*)pXr, (const float*)pW1T, b1, nullptr, (float*)pH,
        HD / 32, FD, FD / 32, 0);

    // GEMM2: out = mask(H @ W2 + b2)
    gemm_tf32_kernel<<<dim3(HD / BN, TT / BM), 256, SMEM_BYTES>>>(
        (const float*)pH, (const float*)pW2T, b2, pad, out,
        FD / 32, HD, 0, 1);
}

// round 10
// speedup vs baseline: 2.0219x; 1.8332x over previous
#include <cuda_runtime.h>
#include <cuda_fp16.h>
#include <cstdint>

// ---------------------------------------------------------------------------
// Problem dims (fixed): B=4, L=4096, H=1024, F=4096
// ---------------------------------------------------------------------------
constexpr int TT = 16384;   // tokens
constexpr int HD = 1024;
constexpr int FD = 4096;

constexpr int BM = 128, BN = 128, BK = 32;
constexpr int STAGES = 3;
constexpr int TILE_HALFS  = BM * BK;           // 4096 fp16 per 128x32 tile
constexpr int TILE_BYTES  = TILE_HALFS * 2;    // 8 KB
constexpr int SMEM_BYTES  = 67584;             // max(3*2*8KB=48KB, epi 128*132*4)

// ---------------------------------------------------------------------------
// Scratch (allocation-free rule: module-scope device globals), fp16 permuted
// ---------------------------------------------------------------------------
__device__ __align__(1024) __half g_Xr [(size_t)TT * HD];   //  32 MB
__device__ __align__(1024) __half g_W1T[(size_t)FD * HD];   //   8 MB
__device__ __align__(1024) __half g_W2T[(size_t)HD * FD];   //   8 MB
__device__ __align__(1024) __half g_H  [(size_t)TT * FD];   // 134 MB

// ---------------------------------------------------------------------------
// Helpers
// ---------------------------------------------------------------------------
__device__ __forceinline__ uint32_t smem_u32(const void* p) {
    uint32_t a;
    asm("{ .reg .u64 t; cvta.to.shared.u64 t, %1; cvt.u32.u64 %0, t; }" : "=r"(a) : "l"(p));
    return a;
}

__device__ __forceinline__ void cp_async16(uint32_t smem_addr, const void* gptr) {
    asm volatile("cp.async.cg.shared.global [%0], [%1], 16;"
                 :: "r"(smem_addr), "l"(gptr) : "memory");
}
#define CP_COMMIT() asm volatile("cp.async.commit_group;" ::: "memory")
#define CP_WAIT(n)  asm volatile("cp.async.wait_group %0;" :: "n"(n) : "memory")

__device__ __forceinline__ void lds128(uint32_t* r, uint32_t addr) {
    asm volatile("ld.shared.v4.b32 {%0,%1,%2,%3}, [%4];"
                 : "=r"(r[0]), "=r"(r[1]), "=r"(r[2]), "=r"(r[3]) : "r"(addr));
}
__device__ __forceinline__ void lds64(uint32_t* r, uint32_t addr) {
    asm volatile("ld.shared.v2.b32 {%0,%1}, [%2];"
                 : "=r"(r[0]), "=r"(r[1]) : "r"(addr));
}

// fp16 MMA: D(f32) += A(f16) * B(f16), 16x8x16
__device__ __forceinline__ void mma_f16(float* c, const uint32_t* a, const uint32_t* b) {
    asm volatile(
        "mma.sync.aligned.m16n8k16.row.col.f32.f16.f16.f32 "
        "{%0,%1,%2,%3}, {%4,%5,%6,%7}, {%8,%9}, {%0,%1,%2,%3};"
        : "+f"(c[0]), "+f"(c[1]), "+f"(c[2]), "+f"(c[3])
        : "r"(a[0]), "r"(a[1]), "r"(a[2]), "r"(a[3]), "r"(b[0]), "r"(b[1]));
}

// ---------------------------------------------------------------------------
// fp16 fragment-order layouts within one [128 rows][32 k] tile (4096 halfs):
//   A: [ks:2][g:8][lane:32][8 fp16]  — thread's 4 A-regs = one 16B chunk
//      chunk order: a0.lo,a0.hi, a1.lo,a1.hi, a2.lo,a2.hi, a3.lo,a3.hi
//      a0=(r,2c..2c+1) a1=(r+8,·) a2=(r,2c+8..9) a3=(r+8,·); lane=lh*4+c2
//   B: [ks:2][ng:16][lane:32][4 fp16] — thread's 2 B-regs = one 8B chunk
//      b0=(k=2c..2c+1, n) b1=(k+8..9, n); lane=(n&7)*4+c2
// ---------------------------------------------------------------------------
__device__ __forceinline__ int off_A16(int r, int kk) {
    int ks = kk >> 4, kr = kk & 15;
    int hk = kr >> 3, c2 = (kr & 7) >> 1, lo = kr & 1;
    int g = r >> 4, rr = r & 15, hm = rr >> 3, lh = rr & 7;
    return (((ks * 8 + g) * 32) + lh * 4 + c2) * 8 + hk * 4 + hm * 2 + lo;
}
__device__ __forceinline__ int off_B16(int n, int kk) {
    int ks = kk >> 4, kr = kk & 15;
    int hk = kr >> 3, c2 = (kr & 7) >> 1, lo = kr & 1;
    int ng = n >> 3, lh = n & 7;
    return (((ks * 16 + ng) * 32) + lh * 4 + c2) * 4 + hk * 2 + lo;
}

// ---------------------------------------------------------------------------
// Prepass: round fp32 -> fp16 (RNE) + permute into tiled fragment layouts
// ---------------------------------------------------------------------------
__global__ void permuteA_kernel(const float* __restrict__ src, __half* __restrict__ dst, int Ksrc) {
    __shared__ __half sp[TILE_HALFS];
    int tid = threadIdx.x;
    const float* s0 = src + (size_t)blockIdx.y * 128 * Ksrc + blockIdx.x * 32;
#pragma unroll
    for (int i = 0; i < 16; i++) {
        int idx = tid + i * 256;
        int r = idx >> 5, kk = idx & 31;
        sp[off_A16(r, kk)] = __float2half_rn(s0[(size_t)r * Ksrc + kk]);
    }
    __syncthreads();
    uint4* d4 = (uint4*)(dst + ((size_t)blockIdx.y * gridDim.x + blockIdx.x) * TILE_HALFS);
#pragma unroll
    for (int i = 0; i < 2; i++) d4[tid + i * 256] = ((uint4*)sp)[tid + i * 256];
}

__global__ void permuteB_kernel(const float* __restrict__ src, __half* __restrict__ dst, int Nsrc) {
    __shared__ __half sp[TILE_HALFS];
    int tid = threadIdx.x;
    const float* s0 = src + (size_t)blockIdx.x * 32 * Nsrc + blockIdx.y * 128;
#pragma unroll
    for (int i = 0; i < 16; i++) {
        int idx = tid + i * 256;
        int kk = idx >> 7, nn = idx & 127;
        sp[off_B16(nn, kk)] = __float2half_rn(s0[(size_t)kk * Nsrc + nn]);
    }
    __syncthreads();
    uint4* d4 = (uint4*)(dst + ((size_t)blockIdx.y * gridDim.x + blockIdx.x) * TILE_HALFS);
#pragma unroll
    for (int i = 0; i < 2; i++) d4[tid + i * 256] = ((uint4*)sp)[tid + i * 256];
}

// ---------------------------------------------------------------------------
// fp16 GEMM on fragment-permuted tiles:
//   mode 0: dst (fp16 A-perm tiles) = fp16(relu(acc + bias))   [H for GEMM2]
//   mode 1: dstf (natural fp32 row-major, width Nnat) = pad ? 0 : acc + bias
// ---------------------------------------------------------------------------
__global__ void __launch_bounds__(256, 2)
gemm_f16_kernel(const __half* __restrict__ A, const __half* __restrict__ Bt,
                const float* __restrict__ bias, const int* __restrict__ padding,
                __half* __restrict__ dstH, float* __restrict__ dstf,
                int numChunks, int Nnat, int ldTiles, int mode) {
    extern __shared__ float smem[];
    const uint32_t smem_base = smem_u32(smem);
    const int tid = threadIdx.x, lane = tid & 31, wid = tid >> 5;
    const int warp_m = wid & 1;        // 2 warps along M
    const int warp_n = wid >> 1;       // 4 warps along N

    const __half* aTiles = A  + (size_t)blockIdx.y * numChunks * TILE_HALFS;
    const __half* bTiles = Bt + (size_t)blockIdx.x * numChunks * TILE_HALFS;

    auto load_stage = [&](int chunk, int s) {
        const __half* aT = aTiles + (size_t)chunk * TILE_HALFS;
        const __half* bT = bTiles + (size_t)chunk * TILE_HALFS;
        uint32_t da = smem_base + s * TILE_BYTES;
        uint32_t db = smem_base + (STAGES + s) * TILE_BYTES;
#pragma unroll
        for (int t = 0; t < 2; t++) {
            int idx = tid + t * 256;
            cp_async16(da + idx * 16, aT + idx * 8);
        }
#pragma unroll
        for (int t = 0; t < 2; t++) {
            int idx = tid + t * 256;
            cp_async16(db + idx * 16, bT + idx * 8);
        }
    };

#pragma unroll
    for (int s = 0; s < STAGES - 1; s++) {
        load_stage(s, s);
        CP_COMMIT();
    }

    float acc[4][4][4];
#pragma unroll
    for (int mt = 0; mt < 4; mt++)
#pragma unroll
        for (int nt = 0; nt < 4; nt++)
#pragma unroll
            for (int j = 0; j < 4; j++) acc[mt][nt][j] = 0.f;

    const uint32_t laneA = lane * 16;
    const uint32_t laneB = lane * 8;

    uint32_t afr[2][4][4], bfr[2][4][2];
    auto load_frags = [&](int ks, int buf, uint32_t aBase, uint32_t bBase) {
#pragma unroll
        for (int mt = 0; mt < 4; mt++)
            lds128(afr[buf][mt], aBase + (uint32_t)((ks * 8 + warp_m * 4 + mt) * 32) * 16u);
#pragma unroll
        for (int nt = 0; nt < 4; nt++)
            lds64(bfr[buf][nt], bBase + (uint32_t)((ks * 16 + warp_n * 4 + nt) * 32) * 8u);
    };

    for (int c = 0; c < numChunks; c++) {
        CP_WAIT(STAGES - 2);
        __syncthreads();                 // single barrier per chunk
        int next = c + STAGES - 1;
        if (next < numChunks) load_stage(next, next % STAGES);
        CP_COMMIT();

        const int s = c % STAGES;
        const uint32_t aBase = smem_base + s * TILE_BYTES + laneA;
        const uint32_t bBase = smem_base + (STAGES + s) * TILE_BYTES + laneB;

        load_frags(0, 0, aBase, bBase);
#pragma unroll
        for (int ks = 0; ks < 2; ks++) {
            const int cur = ks & 1;
            if (ks < 1) load_frags(ks + 1, cur ^ 1, aBase, bBase);
#pragma unroll
            for (int mt = 0; mt < 4; mt++)
#pragma unroll
                for (int nt = 0; nt < 4; nt++)
                    mma_f16(acc[mt][nt], afr[cur][mt], bfr[cur][nt]);
        }
    }
    __syncthreads();                     // protect epilogue smem staging

    if (mode == 0) {
        // Stage fp32 tile to smem (stride 132), then emit fp16 A-perm tiles.
        const int LDSN = 132;
        float* snat = smem;              // 128*132*4 = 67584 B
#pragma unroll
        for (int mt = 0; mt < 4; mt++) {
            int r0 = warp_m * 64 + mt * 16 + (lane >> 2);
#pragma unroll
            for (int hm = 0; hm < 2; hm++) {
                int r = r0 + hm * 8;
#pragma unroll
                for (int nt = 0; nt < 4; nt++) {
                    int col = warp_n * 32 + nt * 8 + (lane & 3) * 2;
                    float2 bv = *reinterpret_cast<const float2*>(bias + blockIdx.x * BN + col);
                    snat[r * LDSN + col]     = fmaxf(acc[mt][nt][hm * 2 + 0] + bv.x, 0.f);
                    snat[r * LDSN + col + 1] = fmaxf(acc[mt][nt][hm * 2 + 1] + bv.y, 0.f);
                }
            }
        }
        __syncthreads();
#pragma unroll
        for (int kt = 0; kt < 4; kt++) {
            uint4* dT = (uint4*)(dstH + ((size_t)blockIdx.y * ldTiles + blockIdx.x * 4 + kt) * TILE_HALFS);
#pragma unroll
            for (int i = 0; i < 2; i++) {
                int chunk = tid + i * 256;           // 16B chunk index (512 per tile)
                int ln = chunk & 31, rest = chunk >> 5;
                int g = rest & 7, ks = rest >> 3;    // ks in {0,1}
                int r0 = g * 16 + (ln >> 2);
                int c0 = kt * 32 + ks * 16 + (ln & 3) * 2;
                __half2 p0 = __floats2half2_rn(snat[r0 * LDSN + c0],       snat[r0 * LDSN + c0 + 1]);
                __half2 p1 = __floats2half2_rn(snat[(r0 + 8) * LDSN + c0], snat[(r0 + 8) * LDSN + c0 + 1]);
                __half2 p2 = __floats2half2_rn(snat[r0 * LDSN + c0 + 8],   snat[r0 * LDSN + c0 + 9]);
                __half2 p3 = __floats2half2_rn(snat[(r0 + 8) * LDSN + c0 + 8], snat[(r0 + 8) * LDSN + c0 + 9]);
                uint4 o;
                o.x = *reinterpret_cast<uint32_t*>(&p0);
                o.y = *reinterpret_cast<uint32_t*>(&p1);
                o.z = *reinterpret_cast<uint32_t*>(&p2);
                o.w = *reinterpret_cast<uint32_t*>(&p3);
                dT[chunk] = o;
            }
        }
    } else {
        const int m0 = blockIdx.y * BM, n0 = blockIdx.x * BN;
#pragma unroll
        for (int mt = 0; mt < 4; mt++) {
            int row0 = m0 + warp_m * 64 + mt * 16 + (lane >> 2);
#pragma unroll
            for (int hm = 0; hm < 2; hm++) {
                int row = row0 + hm * 8;
                int pad = padding[row];
                float* drow = dstf + (size_t)row * Nnat;
#pragma unroll
                for (int nt = 0; nt < 4; nt++) {
                    int col = n0 + warp_n * 32 + nt * 8 + (lane & 3) * 2;
                    float2 bv = *reinterpret_cast<const float2*>(bias + col);
                    float v0 = acc[mt][nt][hm * 2 + 0] + bv.x;
                    float v1 = acc[mt][nt][hm * 2 + 1] + bv.y;
                    if (pad != 0) { v0 = 0.f; v1 = 0.f; }
                    *reinterpret_cast<float2*>(drow + col) = make_float2(v0, v1);
                }
            }
        }
    }
}

// ---------------------------------------------------------------------------
// Host side
// ---------------------------------------------------------------------------
extern "C" void kernel_launch(void* const* d_in, const int* in_sizes, int n_in,
                              void* d_out, int out_size) {
    const float* x   = (const float*)d_in[0];
    const int*   pad = (const int*)  d_in[1];
    const float* W1  = (const float*)d_in[2];
    const float* b1  = (const float*)d_in[3];
    const float* W2  = (const float*)d_in[4];
    const float* b2  = (const float*)d_in[5];
    float*       out = (float*)d_out;

    void *pXr, *pW1T, *pW2T, *pH;
    cudaGetSymbolAddress(&pXr,  g_Xr);
    cudaGetSymbolAddress(&pW1T, g_W1T);
    cudaGetSymbolAddress(&pW2T, g_W2T);
    cudaGetSymbolAddress(&pH,   g_H);

    cudaFuncSetAttribute(gemm_f16_kernel,
                         cudaFuncAttributeMaxDynamicSharedMemorySize, SMEM_BYTES);

    // Prepass: fp32 -> fp16 RNE + permute
    permuteA_kernel<<<dim3(HD / 32, TT / 128), 256>>>(x,  (__half*)pXr,  HD);
    permuteB_kernel<<<dim3(HD / 32, FD / 128), 256>>>(W1, (__half*)pW1T, FD);
    permuteB_kernel<<<dim3(FD / 32, HD / 128), 256>>>(W2, (__half*)pW2T, HD);

    // GEMM1: H(fp16 A-perm) = fp16(relu(X @ W1 + b1))
    gemm_f16_kernel<<<dim3(FD / BN, TT / BM), 256, SMEM_BYTES>>>(
        (const __half*)pXr, (const __half*)pW1T, b1, nullptr,
        (__half*)pH, nullptr, HD / 32, FD, FD / 32, 0);

    // GEMM2: out = mask(H @ W2 + b2)
    gemm_f16_kernel<<<dim3(HD / BN, TT / BM), 256, SMEM_BYTES>>>(
        (const __half*)pH, (const __half*)pW2T, b2, pad,
        nullptr, out, FD / 32, HD, 0, 1);
}